// round 1
// baseline (speedup 1.0000x reference)
#include <cuda_runtime.h>
#include <cuda_bf16.h>
#include <math_constants.h>

// Problem constants
#define B_  10
#define T_  100
#define A_  20
#define NIN 4096
#define NIMG 1024
#define NATT 512
#define NPHYS 256
#define BT  (B_*T_)            // 1000
#define NPAIR 190
#define MPAIR (BT*NPAIR)       // 190000

// Scratch (allocation-free rule: __device__ globals)
__device__ float g_h1[(size_t)MPAIR * NPHYS];
__device__ float g_phys[(size_t)MPAIR * NPHYS];

// ---------------------------------------------------------------------------
// Generic SGEMM: C[M,N] = gatherA[M,K] @ Bw[N,K]^T + bias
//   mode 0: A row r at A + r*K            (plain)
//   mode 1: A row r at A + r*(20*4096)    (glob: x[:,:,0,:])
//   mode 2: A row r at A + ((r/19)*20 + r%19 + 1)*4096   (loc: x[:,:,1:,:])
// BM=BN=128, BK=8, 256 threads, 8x8 per thread, float4 loads, reg prefetch.
// Requires: N % 128 == 0, K % 8 == 0. M edge handled.
// ---------------------------------------------------------------------------
#define BM 128
#define BN 128
#define BK 8
#define TM 8
#define TN 8

__global__ __launch_bounds__(256, 2)
void sgemm_kernel(const float* __restrict__ A,
                  const float* __restrict__ Bw,
                  const float* __restrict__ bias,
                  float* __restrict__ C,
                  int M, int N, int K, int mode)
{
    __shared__ float As[BK][BM];
    __shared__ float Bs[BK][BN];

    const int tid  = threadIdx.x;
    const int row0 = blockIdx.y * BM;
    const int col0 = blockIdx.x * BN;

    // load mapping: lr = row (A) / col (B) within tile, lk = k offset {0,4}
    const int lr = tid & 127;
    const int lk = (tid >> 7) * 4;

    const int arow = row0 + lr;
    const bool arowValid = (arow < M);
    long aoff;
    if (mode == 0)      aoff = (long)arow * K;
    else if (mode == 1) aoff = (long)arow * (long)(A_ * NIN);
    else                aoff = ((long)(arow / 19) * A_ + (arow % 19) + 1) * (long)NIN;

    const float* Aptr = A  + aoff + lk;
    const float* Bptr = Bw + (long)(col0 + lr) * K + lk;

    const int tm = (tid >> 4) * TM;   // 0..120
    const int tn = (tid & 15) * TN;   // 0..120

    float acc[TM][TN];
    #pragma unroll
    for (int i = 0; i < TM; i++)
        #pragma unroll
        for (int j = 0; j < TN; j++) acc[i][j] = 0.f;

    float4 av = arowValid ? *(const float4*)(Aptr) : make_float4(0.f,0.f,0.f,0.f);
    float4 bv = *(const float4*)(Bptr);

    for (int kb = 0; kb < K; kb += BK) {
        As[lk+0][lr] = av.x; As[lk+1][lr] = av.y; As[lk+2][lr] = av.z; As[lk+3][lr] = av.w;
        Bs[lk+0][lr] = bv.x; Bs[lk+1][lr] = bv.y; Bs[lk+2][lr] = bv.z; Bs[lk+3][lr] = bv.w;
        __syncthreads();

        const int kn = kb + BK;
        if (kn < K) {
            av = arowValid ? *(const float4*)(Aptr + kn) : make_float4(0.f,0.f,0.f,0.f);
            bv = *(const float4*)(Bptr + kn);
        }

        #pragma unroll
        for (int kk = 0; kk < BK; kk++) {
            float af[TM], bf[TN];
            #pragma unroll
            for (int i = 0; i < TM; i++) af[i] = As[kk][tm + i];
            #pragma unroll
            for (int j = 0; j < TN; j++) bf[j] = Bs[kk][tn + j];
            #pragma unroll
            for (int i = 0; i < TM; i++)
                #pragma unroll
                for (int j = 0; j < TN; j++)
                    acc[i][j] = fmaf(af[i], bf[j], acc[i][j]);
        }
        __syncthreads();
    }

    // epilogue: bias, store (M edge only; N is tile-aligned)
    #pragma unroll
    for (int j = 0; j < TN; j++) {
        const float bj = bias[col0 + tn + j];
        #pragma unroll
        for (int i = 0; i < TM; i++) {
            const int r = row0 + tm + i;
            if (r < M)
                C[(long)r * N + col0 + tn + j] = acc[i][j] + bj;
        }
    }
}

// ---------------------------------------------------------------------------
// phys stage 1: h1[row][n] = relu( feat(row)[26] . W_phys[n][26] + b[n] )
// feat(row) = concat(wcf[bt, i, :13], wcf[bt, j, :13]) for pair p = row % 190
// CTA: 64 rows x 256 n-columns; W row kept in registers.
// ---------------------------------------------------------------------------
__global__ __launch_bounds__(256)
void phys1_kernel(const float* __restrict__ wcf,   // (BT, 20, 13)
                  const float* __restrict__ Wp,    // (256, 26)
                  const float* __restrict__ bp,    // (256)
                  float* __restrict__ h1)          // (MPAIR, 256)
{
    __shared__ float feat[64][26];
    const int tid  = threadIdx.x;
    const int row0 = blockIdx.x * 64;

    // gather pair features
    for (int e = tid; e < 64 * 26; e += 256) {
        const int r = e / 26, k = e % 26;
        const int row = row0 + r;
        float v = 0.f;
        if (row < MPAIR) {
            const int bt = row / NPAIR;
            const int p  = row % NPAIR;
            // invert lex pair index -> (i, j), i<j
            int i2 = 0, rem = p;
            while (rem >= 19 - i2) { rem -= 19 - i2; i2++; }
            const int j2 = i2 + 1 + rem;
            const int ag = (k < 13) ? i2 : j2;
            const int kk = (k < 13) ? k : k - 13;
            v = wcf[(long)bt * (A_ * 13) + ag * 13 + kk];
        }
        feat[r][k] = v;
    }
    __syncthreads();

    const int n = tid;               // output feature
    float w[26];
    #pragma unroll
    for (int k = 0; k < 26; k++) w[k] = Wp[n * 26 + k];
    const float bn = bp[n];

    const int rmax = min(64, MPAIR - row0);
    for (int r = 0; r < rmax; r++) {
        float acc = bn;
        #pragma unroll
        for (int k = 0; k < 26; k++) acc = fmaf(feat[r][k], w[k], acc);
        h1[(long)(row0 + r) * NPHYS + n] = fmaxf(acc, 0.f);
    }
}

// ---------------------------------------------------------------------------
// per-agent max over the 19 pairs containing agent k
// one CTA per (bt, k) cell; thread = feature n. Coalesced reads/writes.
// ---------------------------------------------------------------------------
__global__ __launch_bounds__(256)
void segmax_kernel(const float* __restrict__ phys,  // (MPAIR, 256)
                   float* __restrict__ out)         // (BT, 20, 256)
{
    const int cell = blockIdx.x;         // bt*20 + k
    const int bt = cell / A_, k = cell % A_;
    const int n = threadIdx.x;
    const float* base = phys + (long)bt * NPAIR * NPHYS;

    float m = -CUDART_INF_F;
    #pragma unroll
    for (int o = 0; o < A_; o++) {
        if (o == k) continue;
        const int i = (o < k) ? o : k;
        const int j = (o < k) ? k : o;
        const int p = i * 19 - (i * (i - 1)) / 2 + (j - i - 1);
        m = fmaxf(m, base[(long)p * NPHYS + n]);
    }
    out[(long)cell * NPHYS + n] = m;
}

// ---------------------------------------------------------------------------
extern "C" void kernel_launch(void* const* d_in, const int* in_sizes, int n_in,
                              void* d_out, int out_size)
{
    const float* x    = (const float*)d_in[0];   // (10,100,20,4096)
    const float* wcf  = (const float*)d_in[1];   // (10,100,20,13)
    const float* Wg   = (const float*)d_in[2];   // (1024,4096)
    const float* bg   = (const float*)d_in[3];
    const float* Wl   = (const float*)d_in[4];   // (512,4096)
    const float* bl   = (const float*)d_in[5];
    const float* Wp   = (const float*)d_in[6];   // (256,26)
    const float* bp   = (const float*)d_in[7];
    const float* W3   = (const float*)d_in[8];   // (256,256)
    const float* b3   = (const float*)d_in[9];

    float* out      = (float*)d_out;
    float* out_glob = out;                              // (1000,1024)
    float* out_loc  = out + (size_t)BT * NIMG;          // (19000,512)
    float* out_agt  = out_loc + (size_t)BT * 19 * NATT; // (20000,256)

    float* h1p = nullptr, *physp = nullptr;
    cudaGetSymbolAddress((void**)&h1p,   g_h1);
    cudaGetSymbolAddress((void**)&physp, g_phys);

    // glob: M=1000, N=1024, K=4096, mode 1
    sgemm_kernel<<<dim3(NIMG / BN, (BT + BM - 1) / BM), 256>>>(
        x, Wg, bg, out_glob, BT, NIMG, NIN, 1);

    // loc: M=19000, N=512, K=4096, mode 2
    sgemm_kernel<<<dim3(NATT / BN, (BT * 19 + BM - 1) / BM), 256>>>(
        x, Wl, bl, out_loc, BT * 19, NATT, NIN, 2);

    // phys stage 1 (gather + small GEMM + relu)
    phys1_kernel<<<(MPAIR + 63) / 64, 256>>>(wcf, Wp, bp, h1p);

    // phys stage 2: M=190000, N=256, K=256, mode 0
    sgemm_kernel<<<dim3(NPHYS / BN, (MPAIR + BM - 1) / BM), 256>>>(
        h1p, W3, b3, physp, MPAIR, NPHYS, NPHYS, 0);

    // per-agent segment max
    segmax_kernel<<<BT * A_, 256>>>(physp, out_agt);
}

// round 3
// speedup vs baseline: 3.7510x; 3.7510x over previous
#include <cuda_runtime.h>
#include <cstdint>
#include <math_constants.h>

// ---------------------------------------------------------------------------
// Problem constants
// ---------------------------------------------------------------------------
#define B_  10
#define T_  100
#define A_  20
#define NIN 4096
#define NIMG 1024
#define NATT 512
#define NPHYS 256
#define BT  (B_*T_)            // 1000
#define NPAIR 190
#define MPAIR (BT*NPAIR)       // 190000

// Scratch (allocation-free rule: __device__ globals)
__device__ __align__(256) float g_h1[(size_t)MPAIR * NPHYS];
__device__ __align__(256) float g_phys[(size_t)MPAIR * NPHYS];

// ---------------------------------------------------------------------------
// PTX helpers (sm_80-class ISA only — tcgen05 is rejected by this toolchain)
// ---------------------------------------------------------------------------
__device__ __forceinline__ uint32_t smem_u32(const void* p) {
    uint32_t a;
    asm("{ .reg .u64 t; cvta.to.shared.u64 t, %1; cvt.u32.u64 %0, t; }"
        : "=r"(a) : "l"(p));
    return a;
}

__device__ __forceinline__ void ldsm_x4(uint32_t* r, uint32_t addr) {
    asm volatile("ldmatrix.sync.aligned.m8n8.x4.shared.b16 {%0,%1,%2,%3}, [%4];"
                 : "=r"(r[0]), "=r"(r[1]), "=r"(r[2]), "=r"(r[3]) : "r"(addr));
}

__device__ __forceinline__ uint32_t f2tf32(uint32_t x) {
    uint32_t y;
    asm("cvt.rna.tf32.f32 %0, %1;" : "=r"(y) : "f"(__uint_as_float(x)));
    return y;
}

__device__ __forceinline__ void mma_tf32(float* d, const uint32_t* a,
                                         uint32_t b0, uint32_t b1) {
    asm volatile(
        "mma.sync.aligned.m16n8k8.row.col.f32.tf32.tf32.f32 "
        "{%0,%1,%2,%3}, {%4,%5,%6,%7}, {%8,%9}, {%0,%1,%2,%3};"
        : "+f"(d[0]), "+f"(d[1]), "+f"(d[2]), "+f"(d[3])
        : "r"(a[0]), "r"(a[1]), "r"(a[2]), "r"(a[3]), "r"(b0), "r"(b1));
}

__device__ __forceinline__ void cp_async16(uint32_t dst, const void* src, int sz) {
    asm volatile("cp.async.cg.shared.global [%0], [%1], 16, %2;"
                 :: "r"(dst), "l"(src), "r"(sz));
}

// ---------------------------------------------------------------------------
// tf32 mma.sync GEMM: C[M,N] = gatherA[M,K] @ Bw[N,K]^T + bias
//   mode 0: A row r at A + r*K
//   mode 1: A row r at A + r*(20*4096)                    (glob: x[:,:,0,:])
//   mode 2: A row r at A + ((r/19)*20 + r%19 + 1)*4096    (loc: x[:,:,1:,:])
// CTA tile 128x256, BK=32, 3-stage cp.async pipeline, 8 warps x (64x64).
// Requires N % 256 == 0, K % 32 == 0. M edge handled via zfill + store mask.
// ---------------------------------------------------------------------------
#define BK 32
#define STAGE_BYTES 49152          // A 16KB + B 32KB
#define STG_A 0
#define STG_B 16384
#define SM_TOTAL (3 * STAGE_BYTES) // 147456

__global__ __launch_bounds__(256, 1)
void mma_gemm(const float* __restrict__ A, const float* __restrict__ Bw,
              const float* __restrict__ bias, float* __restrict__ C,
              int M, int N, int K, int mode)
{
    extern __shared__ char smem[];
    const uint32_t sb = smem_u32(smem);
    const int tid  = threadIdx.x;
    const int wid  = tid >> 5;
    const int lane = tid & 31;
    const int row0 = blockIdx.y * 128;
    const int col0 = blockIdx.x * 256;
    const int wm = (wid & 1) * 64;   // warp M offset in tile
    const int wn = (wid >> 1) * 64;  // warp N offset in tile

    // ---- cp.async slot precompute: 4 A-chunks + 8 B-chunks of 16B ----
    long aoff[4]; int avalid[4]; uint32_t dstA[4];
    #pragma unroll
    for (int j = 0; j < 4; j++) {
        const int e = tid + j * 256;        // 0..1023
        const int r = e >> 3, kc = e & 7;
        dstA[j] = sb + STG_A + (uint32_t)(r * 128 + ((kc ^ (r & 7)) * 16));
        const int am = row0 + r;
        avalid[j] = (am < M) ? 16 : 0;
        const int amc = (am < M) ? am : 0;
        long ao;
        if (mode == 0)      ao = (long)amc * K;
        else if (mode == 1) ao = (long)amc * (long)(A_ * NIN);
        else                ao = ((long)(amc / 19) * A_ + (amc % 19) + 1) * (long)NIN;
        aoff[j] = ao + kc * 4;
    }
    long boff[8]; uint32_t dstB[8];
    #pragma unroll
    for (int j = 0; j < 8; j++) {
        const int e = tid + j * 256;        // 0..2047
        const int r = e >> 3, kc = e & 7;   // r: 0..255
        dstB[j] = sb + STG_B + (uint32_t)(r * 128 + ((kc ^ (r & 7)) * 16));
        boff[j] = (long)(col0 + r) * K + kc * 4;
    }

    // ---- ldmatrix per-thread address components ----
    const int arow = lane & 15;            // A: row within 16-row tile
    const int agrp = lane >> 4;            // A: 16B-group parity
    const int brow = (lane & 7) + ((lane >> 4) << 3);  // B: row within 16
    const int bgrp = (lane >> 3) & 1;

    float d[4][8][4];
    #pragma unroll
    for (int mt = 0; mt < 4; mt++)
        #pragma unroll
        for (int nt = 0; nt < 8; nt++)
            #pragma unroll
            for (int q = 0; q < 4; q++) d[mt][nt][q] = 0.f;

    const int NK = K / BK;

    // ---- prologue: stages 0,1 ----
    #pragma unroll
    for (int s = 0; s < 2; s++) {
        const uint32_t so = s * STAGE_BYTES;
        const int koff = s * BK;
        #pragma unroll
        for (int j = 0; j < 4; j++) cp_async16(dstA[j] + so, A + aoff[j] + koff, avalid[j]);
        #pragma unroll
        for (int j = 0; j < 8; j++) cp_async16(dstB[j] + so, Bw + boff[j] + koff, 16);
        asm volatile("cp.async.commit_group;" ::: "memory");
    }

    #pragma unroll 1
    for (int kb = 0; kb < NK; kb++) {
        asm volatile("cp.async.wait_group 1;" ::: "memory");
        __syncthreads();

        // issue stage kb+2 (into buffer just vacated by compute kb-1)
        if (kb + 2 < NK) {
            const uint32_t so = ((kb + 2) % 3) * STAGE_BYTES;
            const int koff = (kb + 2) * BK;
            #pragma unroll
            for (int j = 0; j < 4; j++) cp_async16(dstA[j] + so, A + aoff[j] + koff, avalid[j]);
            #pragma unroll
            for (int j = 0; j < 8; j++) cp_async16(dstB[j] + so, Bw + boff[j] + koff, 16);
        }
        asm volatile("cp.async.commit_group;" ::: "memory");

        // compute on stage kb%3
        const uint32_t sa = sb + STG_A + (kb % 3) * STAGE_BYTES;
        const uint32_t sbs = sb + STG_B + (kb % 3) * STAGE_BYTES;
        #pragma unroll
        for (int kk = 0; kk < 4; kk++) {
            uint32_t afr[4][4];
            #pragma unroll
            for (int mt = 0; mt < 4; mt++) {
                const int r = wm + mt * 16 + arow;
                const uint32_t addr = sa + r * 128 + (((2 * kk + agrp) ^ (r & 7)) * 16);
                ldsm_x4(afr[mt], addr);
                #pragma unroll
                for (int q = 0; q < 4; q++) afr[mt][q] = f2tf32(afr[mt][q]);
            }
            uint32_t bfr[4][4];
            #pragma unroll
            for (int nt2 = 0; nt2 < 4; nt2++) {
                const int r = wn + nt2 * 16 + brow;
                const uint32_t addr = sbs + r * 128 + (((2 * kk + bgrp) ^ (r & 7)) * 16);
                ldsm_x4(bfr[nt2], addr);
                #pragma unroll
                for (int q = 0; q < 4; q++) bfr[nt2][q] = f2tf32(bfr[nt2][q]);
            }
            #pragma unroll
            for (int mt = 0; mt < 4; mt++)
                #pragma unroll
                for (int nt = 0; nt < 8; nt++)
                    mma_tf32(d[mt][nt], afr[mt],
                             bfr[nt >> 1][(nt & 1) * 2], bfr[nt >> 1][(nt & 1) * 2 + 1]);
        }
    }

    // ---- epilogue: bias + store (fp32 accum in regs) ----
    #pragma unroll
    for (int mt = 0; mt < 4; mt++) {
        const int rlo = row0 + wm + mt * 16 + (lane >> 2);
        const int rhi = rlo + 8;
        #pragma unroll
        for (int nt = 0; nt < 8; nt++) {
            const int col = col0 + wn + nt * 8 + (lane & 3) * 2;
            const float2 bv = *(const float2*)(bias + col);
            if (rlo < M) {
                float2 v; v.x = d[mt][nt][0] + bv.x; v.y = d[mt][nt][1] + bv.y;
                *(float2*)(C + (long)rlo * N + col) = v;
            }
            if (rhi < M) {
                float2 v; v.x = d[mt][nt][2] + bv.x; v.y = d[mt][nt][3] + bv.y;
                *(float2*)(C + (long)rhi * N + col) = v;
            }
        }
    }
}

// ---------------------------------------------------------------------------
// phys stage 1: h1[row][n] = relu( feat(row)[26] . W_phys[n][26] + b[n] )
// ---------------------------------------------------------------------------
__global__ __launch_bounds__(256)
void phys1_kernel(const float* __restrict__ wcf,   // (BT, 20, 13)
                  const float* __restrict__ Wp,    // (256, 26)
                  const float* __restrict__ bp,    // (256)
                  float* __restrict__ h1)          // (MPAIR, 256)
{
    __shared__ float feat[64][26];
    const int tid  = threadIdx.x;
    const int row0 = blockIdx.x * 64;

    for (int e = tid; e < 64 * 26; e += 256) {
        const int r = e / 26, k = e % 26;
        const int row = row0 + r;
        float v = 0.f;
        if (row < MPAIR) {
            const int bt = row / NPAIR;
            const int p  = row % NPAIR;
            int i2 = 0, rem = p;
            while (rem >= 19 - i2) { rem -= 19 - i2; i2++; }
            const int j2 = i2 + 1 + rem;
            const int ag = (k < 13) ? i2 : j2;
            const int kk = (k < 13) ? k : k - 13;
            v = wcf[(long)bt * (A_ * 13) + ag * 13 + kk];
        }
        feat[r][k] = v;
    }
    __syncthreads();

    const int n = tid;
    float w[26];
    #pragma unroll
    for (int k = 0; k < 26; k++) w[k] = Wp[n * 26 + k];
    const float bn = bp[n];

    const int rmax = min(64, MPAIR - row0);
    for (int r = 0; r < rmax; r++) {
        float acc = bn;
        #pragma unroll
        for (int k = 0; k < 26; k++) acc = fmaf(feat[r][k], w[k], acc);
        h1[(long)(row0 + r) * NPHYS + n] = fmaxf(acc, 0.f);
    }
}

// ---------------------------------------------------------------------------
// per-agent max over the 19 pairs containing agent k
// ---------------------------------------------------------------------------
__global__ __launch_bounds__(256)
void segmax_kernel(const float* __restrict__ phys,  // (MPAIR, 256)
                   float* __restrict__ out)         // (BT, 20, 256)
{
    const int cell = blockIdx.x;
    const int bt = cell / A_, k = cell % A_;
    const int n = threadIdx.x;
    const float* base = phys + (long)bt * NPAIR * NPHYS;

    float m = -CUDART_INF_F;
    #pragma unroll
    for (int o = 0; o < A_; o++) {
        if (o == k) continue;
        const int i = (o < k) ? o : k;
        const int j = (o < k) ? k : o;
        const int p = i * 19 - (i * (i - 1)) / 2 + (j - i - 1);
        m = fmaxf(m, base[(long)p * NPHYS + n]);
    }
    out[(long)cell * NPHYS + n] = m;
}

// ---------------------------------------------------------------------------
extern "C" void kernel_launch(void* const* d_in, const int* in_sizes, int n_in,
                              void* d_out, int out_size)
{
    const float* x    = (const float*)d_in[0];
    const float* wcf  = (const float*)d_in[1];
    const float* Wg   = (const float*)d_in[2];
    const float* bg   = (const float*)d_in[3];
    const float* Wl   = (const float*)d_in[4];
    const float* bl   = (const float*)d_in[5];
    const float* Wp   = (const float*)d_in[6];
    const float* bp   = (const float*)d_in[7];
    const float* W3   = (const float*)d_in[8];
    const float* b3   = (const float*)d_in[9];

    float* out      = (float*)d_out;
    float* out_glob = out;                               // (1000,1024)
    float* out_loc  = out + (size_t)BT * NIMG;           // (19000,512)
    float* out_agt  = out_loc + (size_t)BT * 19 * NATT;  // (20000,256)

    float* h1p = nullptr, *physp = nullptr;
    cudaGetSymbolAddress((void**)&h1p,   g_h1);
    cudaGetSymbolAddress((void**)&physp, g_phys);

    cudaFuncSetAttribute(mma_gemm, cudaFuncAttributeMaxDynamicSharedMemorySize, SM_TOTAL);

    // glob: M=1000, N=1024, K=4096, mode 1
    mma_gemm<<<dim3(NIMG / 256, (BT + 127) / 128), 256, SM_TOTAL>>>(
        x, Wg, bg, out_glob, BT, NIMG, NIN, 1);

    // loc: M=19000, N=512, K=4096, mode 2
    mma_gemm<<<dim3(NATT / 256, (BT * 19 + 127) / 128), 256, SM_TOTAL>>>(
        x, Wl, bl, out_loc, BT * 19, NATT, NIN, 2);

    // phys stage 1 (gather + tiny GEMM + relu)
    phys1_kernel<<<(MPAIR + 63) / 64, 256>>>(wcf, Wp, bp, h1p);

    // phys stage 2: M=190000, N=256, K=256, mode 0
    mma_gemm<<<dim3(NPHYS / 256, (MPAIR + 127) / 128), 256, SM_TOTAL>>>(
        h1p, W3, b3, physp, MPAIR, NPHYS, NPHYS, 0);

    // per-agent segment max
    segmax_kernel<<<BT * A_, 256>>>(physp, out_agt);
}

// round 4
// speedup vs baseline: 4.1762x; 1.1134x over previous
#include <cuda_runtime.h>
#include <cstdint>
#include <math_constants.h>

// ---------------------------------------------------------------------------
// Problem constants
// ---------------------------------------------------------------------------
#define B_  10
#define T_  100
#define A_  20
#define NIN 4096
#define NIMG 1024
#define NATT 512
#define NPHYS 256
#define BT  (B_*T_)            // 1000
#define NPAIR 190
#define MPAIR (BT*NPAIR)       // 190000

// Scratch (allocation-free rule: __device__ globals)
__device__ __align__(256) float g_h1[(size_t)MPAIR * NPHYS];
__device__ __align__(256) float g_phys[(size_t)MPAIR * NPHYS];

// ---------------------------------------------------------------------------
// PTX helpers (sm_80-class ISA — tcgen05 is rejected by this toolchain)
// ---------------------------------------------------------------------------
__device__ __forceinline__ uint32_t smem_u32(const void* p) {
    uint32_t a;
    asm("{ .reg .u64 t; cvta.to.shared.u64 t, %1; cvt.u32.u64 %0, t; }"
        : "=r"(a) : "l"(p));
    return a;
}

__device__ __forceinline__ void ldsm_x4(uint32_t* r, uint32_t addr) {
    asm volatile("ldmatrix.sync.aligned.m8n8.x4.shared.b16 {%0,%1,%2,%3}, [%4];"
                 : "=r"(r[0]), "=r"(r[1]), "=r"(r[2]), "=r"(r[3]) : "r"(addr));
}

__device__ __forceinline__ uint32_t f2tf32(uint32_t x) {
    uint32_t y;
    asm("cvt.rna.tf32.f32 %0, %1;" : "=r"(y) : "f"(__uint_as_float(x)));
    return y;
}

__device__ __forceinline__ void mma_tf32(float* d, const uint32_t* a,
                                         uint32_t b0, uint32_t b1) {
    asm volatile(
        "mma.sync.aligned.m16n8k8.row.col.f32.tf32.tf32.f32 "
        "{%0,%1,%2,%3}, {%4,%5,%6,%7}, {%8,%9}, {%0,%1,%2,%3};"
        : "+f"(d[0]), "+f"(d[1]), "+f"(d[2]), "+f"(d[3])
        : "r"(a[0]), "r"(a[1]), "r"(a[2]), "r"(a[3]), "r"(b0), "r"(b1));
}

__device__ __forceinline__ void cp_async16(uint32_t dst, const void* src, int sz) {
    asm volatile("cp.async.cg.shared.global [%0], [%1], 16, %2;"
                 :: "r"(dst), "l"(src), "r"(sz));
}

// ---------------------------------------------------------------------------
// tf32 GEMM core: C[M,N] = gatherA[M,K] @ Bw[N,K]^T + bias
//   mode 0: A row r at A + r*K
//   mode 1: A row r at A + r*(20*4096)                    (glob: x[:,:,0,:])
//   mode 2: A row r at A + ((r/19)*20 + r%19 + 1)*4096    (loc: x[:,:,1:,:])
// CTA tile 128x128, BK=32, 3-stage cp.async, 8 warps x (32x64), 2 CTAs/SM.
// Requires N % 128 == 0, K % 32 == 0. M edge via zfill + store mask.
// ---------------------------------------------------------------------------
#define BK 32
#define STG_A 0
#define STG_B 16384
#define STAGE_BYTES 32768
#define SM_TOTAL (3 * STAGE_BYTES)   // 98304

struct GemmDesc {
    const float* A; const float* Bw; const float* bias; float* C;
    int M, N, K, mode;
};

__device__ __forceinline__ void gemm_core(const GemmDesc g, int idx,
                                          uint32_t sb)
{
    const float* __restrict__ A  = g.A;
    const float* __restrict__ Bw = g.Bw;
    const int M = g.M, N = g.N, K = g.K, mode = g.mode;

    const int nx   = N >> 7;
    const int row0 = (idx / nx) * 128;
    const int col0 = (idx % nx) * 128;

    const int tid  = threadIdx.x;
    const int wid  = tid >> 5;
    const int lane = tid & 31;
    const int wm = (wid & 3) * 32;    // warp M offset
    const int wn = (wid >> 2) * 64;   // warp N offset

    // ---- cp.async slots: 4 A-chunks + 4 B-chunks of 16B per stage ----
    long aoff[4]; int avalid[4]; uint32_t dstA[4];
    long boff[4]; uint32_t dstB[4];
    #pragma unroll
    for (int j = 0; j < 4; j++) {
        const int e = tid + j * 256;        // 0..1023
        const int r = e >> 3, kc = e & 7;
        const uint32_t sw = (uint32_t)(r * 128 + ((kc ^ (r & 7)) * 16));
        dstA[j] = sb + STG_A + sw;
        dstB[j] = sb + STG_B + sw;
        const int am = row0 + r;
        avalid[j] = (am < M) ? 16 : 0;
        const int amc = (am < M) ? am : 0;
        long ao;
        if (mode == 0)      ao = (long)amc * K;
        else if (mode == 1) ao = (long)amc * (long)(A_ * NIN);
        else                ao = ((long)(amc / 19) * A_ + (amc % 19) + 1) * (long)NIN;
        aoff[j] = ao + kc * 4;
        boff[j] = (long)(col0 + r) * K + kc * 4;
    }

    // ---- ldmatrix per-thread address components ----
    const int arow = lane & 15;
    const int agrp = lane >> 4;
    const int brow = (lane & 7) + ((lane >> 4) << 3);
    const int bgrp = (lane >> 3) & 1;

    float d[2][8][4];
    #pragma unroll
    for (int mt = 0; mt < 2; mt++)
        #pragma unroll
        for (int nt = 0; nt < 8; nt++)
            #pragma unroll
            for (int q = 0; q < 4; q++) d[mt][nt][q] = 0.f;

    const int NK = K / BK;

    // ---- prologue: stages 0,1 ----
    #pragma unroll
    for (int s = 0; s < 2; s++) {
        const uint32_t so = s * STAGE_BYTES;
        const int koff = s * BK;
        #pragma unroll
        for (int j = 0; j < 4; j++) {
            cp_async16(dstA[j] + so, A + aoff[j] + koff, avalid[j]);
            cp_async16(dstB[j] + so, Bw + boff[j] + koff, 16);
        }
        asm volatile("cp.async.commit_group;" ::: "memory");
    }

    #pragma unroll 1
    for (int kb = 0; kb < NK; kb++) {
        asm volatile("cp.async.wait_group 1;" ::: "memory");
        __syncthreads();

        if (kb + 2 < NK) {
            const uint32_t so = ((kb + 2) % 3) * STAGE_BYTES;
            const int koff = (kb + 2) * BK;
            #pragma unroll
            for (int j = 0; j < 4; j++) {
                cp_async16(dstA[j] + so, A + aoff[j] + koff, avalid[j]);
                cp_async16(dstB[j] + so, Bw + boff[j] + koff, 16);
            }
        }
        asm volatile("cp.async.commit_group;" ::: "memory");

        const uint32_t sa  = sb + STG_A + (kb % 3) * STAGE_BYTES;
        const uint32_t sbs = sb + STG_B + (kb % 3) * STAGE_BYTES;
        #pragma unroll
        for (int kk = 0; kk < 4; kk++) {
            uint32_t afr[2][4];
            #pragma unroll
            for (int mt = 0; mt < 2; mt++) {
                const int r = wm + mt * 16 + arow;
                const uint32_t addr = sa + r * 128 + (((2 * kk + agrp) ^ (r & 7)) * 16);
                ldsm_x4(afr[mt], addr);
                #pragma unroll
                for (int q = 0; q < 4; q++) afr[mt][q] = f2tf32(afr[mt][q]);
            }
            uint32_t bfr[4][4];
            #pragma unroll
            for (int nt2 = 0; nt2 < 4; nt2++) {
                const int r = wn + nt2 * 16 + brow;
                const uint32_t addr = sbs + r * 128 + (((2 * kk + bgrp) ^ (r & 7)) * 16);
                ldsm_x4(bfr[nt2], addr);
                #pragma unroll
                for (int q = 0; q < 4; q++) bfr[nt2][q] = f2tf32(bfr[nt2][q]);
            }
            #pragma unroll
            for (int mt = 0; mt < 2; mt++)
                #pragma unroll
                for (int nt = 0; nt < 8; nt++)
                    mma_tf32(d[mt][nt], afr[mt],
                             bfr[nt >> 1][(nt & 1) * 2], bfr[nt >> 1][(nt & 1) * 2 + 1]);
        }
    }

    // ---- epilogue ----
    float* __restrict__ C = g.C;
    const float* __restrict__ bias = g.bias;
    #pragma unroll
    for (int mt = 0; mt < 2; mt++) {
        const int rlo = row0 + wm + mt * 16 + (lane >> 2);
        const int rhi = rlo + 8;
        #pragma unroll
        for (int nt = 0; nt < 8; nt++) {
            const int col = col0 + wn + nt * 8 + (lane & 3) * 2;
            const float2 bv = *(const float2*)(bias + col);
            if (rlo < M) {
                float2 v; v.x = d[mt][nt][0] + bv.x; v.y = d[mt][nt][1] + bv.y;
                *(float2*)(C + (long)rlo * N + col) = v;
            }
            if (rhi < M) {
                float2 v; v.x = d[mt][nt][2] + bv.x; v.y = d[mt][nt][3] + bv.y;
                *(float2*)(C + (long)rhi * N + col) = v;
            }
        }
    }
}

// Fused dispatch: CTAs [0, split) run d0, CTAs [split, grid) run d1.
__global__ __launch_bounds__(256, 2)
void fused_gemm(const GemmDesc d0, const GemmDesc d1, int split)
{
    extern __shared__ char smem[];
    const uint32_t sb = smem_u32(smem);
    const int i = blockIdx.x;
    if (i < split) gemm_core(d0, i, sb);
    else           gemm_core(d1, i - split, sb);
}

// ---------------------------------------------------------------------------
// phys stage 1: h1[row][n] = relu( feat(row)[26] . W_phys[n][26] + b[n] )
// ---------------------------------------------------------------------------
__global__ __launch_bounds__(256)
void phys1_kernel(const float* __restrict__ wcf,   // (BT, 20, 13)
                  const float* __restrict__ Wp,    // (256, 26)
                  const float* __restrict__ bp,    // (256)
                  float* __restrict__ h1)          // (MPAIR, 256)
{
    __shared__ float feat[64][26];
    const int tid  = threadIdx.x;
    const int row0 = blockIdx.x * 64;

    for (int e = tid; e < 64 * 26; e += 256) {
        const int r = e / 26, k = e % 26;
        const int row = row0 + r;
        float v = 0.f;
        if (row < MPAIR) {
            const int bt = row / NPAIR;
            const int p  = row % NPAIR;
            int i2 = 0, rem = p;
            while (rem >= 19 - i2) { rem -= 19 - i2; i2++; }
            const int j2 = i2 + 1 + rem;
            const int ag = (k < 13) ? i2 : j2;
            const int kk = (k < 13) ? k : k - 13;
            v = wcf[(long)bt * (A_ * 13) + ag * 13 + kk];
        }
        feat[r][k] = v;
    }
    __syncthreads();

    const int n = tid;
    float w[26];
    #pragma unroll
    for (int k = 0; k < 26; k++) w[k] = Wp[n * 26 + k];
    const float bn = bp[n];

    const int rmax = min(64, MPAIR - row0);
    for (int r = 0; r < rmax; r++) {
        float acc = bn;
        #pragma unroll
        for (int k = 0; k < 26; k++) acc = fmaf(feat[r][k], w[k], acc);
        h1[(long)(row0 + r) * NPHYS + n] = fmaxf(acc, 0.f);
    }
}

// ---------------------------------------------------------------------------
// segmax: one CTA per bt. Stage phys[bt] (190x256 = 194KB) in smem, then
// compute all 20 agents' maxes. Each phys element hits DRAM exactly once.
// ---------------------------------------------------------------------------
#define SEG_SMEM (NPAIR * NPHYS * 4)   // 194560

__global__ __launch_bounds__(512, 1)
void segmax_smem(const float* __restrict__ phys,  // (MPAIR, 256)
                 float* __restrict__ out)         // (BT, 20, 256)
{
    extern __shared__ float tile[];    // [190][256]
    const int bt  = blockIdx.x;
    const int tid = threadIdx.x;
    const float4* src = (const float4*)(phys + (long)bt * NPAIR * NPHYS);

    #pragma unroll
    for (int i = 0; i < (NPAIR * NPHYS / 4 + 511) / 512; i++) {
        const int e = tid + i * 512;
        if (e < NPAIR * NPHYS / 4) ((float4*)tile)[e] = src[e];
    }
    __syncthreads();

    // 20*256 = 5120 outputs, 10 per thread
    #pragma unroll
    for (int i = 0; i < 10; i++) {
        const int o = tid + i * 512;
        const int k = o >> 8, n = o & 255;
        float m = -CUDART_INF_F;
        #pragma unroll
        for (int other = 0; other < A_; other++) {
            if (other == k) continue;
            const int lo = (other < k) ? other : k;
            const int hi = (other < k) ? k : other;
            const int p = lo * 19 - (lo * (lo - 1)) / 2 + (hi - lo - 1);
            m = fmaxf(m, tile[p * NPHYS + n]);
        }
        out[((long)bt * A_ + k) * NPHYS + n] = m;
    }
}

// ---------------------------------------------------------------------------
extern "C" void kernel_launch(void* const* d_in, const int* in_sizes, int n_in,
                              void* d_out, int out_size)
{
    const float* x    = (const float*)d_in[0];
    const float* wcf  = (const float*)d_in[1];
    const float* Wg   = (const float*)d_in[2];
    const float* bg   = (const float*)d_in[3];
    const float* Wl   = (const float*)d_in[4];
    const float* bl   = (const float*)d_in[5];
    const float* Wp   = (const float*)d_in[6];
    const float* bp   = (const float*)d_in[7];
    const float* W3   = (const float*)d_in[8];
    const float* b3   = (const float*)d_in[9];

    float* out      = (float*)d_out;
    float* out_glob = out;                               // (1000,1024)
    float* out_loc  = out + (size_t)BT * NIMG;           // (19000,512)
    float* out_agt  = out_loc + (size_t)BT * 19 * NATT;  // (20000,256)

    float* h1p = nullptr, *physp = nullptr;
    cudaGetSymbolAddress((void**)&h1p,   g_h1);
    cudaGetSymbolAddress((void**)&physp, g_phys);

    cudaFuncSetAttribute(fused_gemm, cudaFuncAttributeMaxDynamicSharedMemorySize, SM_TOTAL);
    cudaFuncSetAttribute(segmax_smem, cudaFuncAttributeMaxDynamicSharedMemorySize, SEG_SMEM);

    // phys stage 1 first (independent)
    phys1_kernel<<<(MPAIR + 63) / 64, 256>>>(wcf, Wp, bp, h1p);

    // loc + glob merged into one launch
    {
        GemmDesc dl = { x, Wl, bl, out_loc, BT * 19, NATT, NIN, 2 };
        GemmDesc dg = { x, Wg, bg, out_glob, BT, NIMG, NIN, 1 };
        const int nLoc  = (NATT / 128) * ((BT * 19 + 127) / 128);   // 4*149 = 596
        const int nGlob = (NIMG / 128) * ((BT + 127) / 128);        // 8*8   = 64
        fused_gemm<<<nLoc + nGlob, 256, SM_TOTAL>>>(dl, dg, nLoc);
    }

    // phys stage 2: M=190000, N=256, K=256
    {
        GemmDesc dp = { h1p, W3, b3, physp, MPAIR, NPHYS, NPHYS, 0 };
        const int nP = (NPHYS / 128) * ((MPAIR + 127) / 128);       // 2*1485 = 2970
        fused_gemm<<<nP, 256, SM_TOTAL>>>(dp, dp, nP);
    }

    // per-agent segment max (smem-staged, single DRAM pass)
    segmax_smem<<<BT, 512, SEG_SMEM>>>(physp, out_agt);
}

// round 6
// speedup vs baseline: 4.2483x; 1.0173x over previous
#include <cuda_runtime.h>
#include <cstdint>
#include <math_constants.h>

// ---------------------------------------------------------------------------
// Problem constants
// ---------------------------------------------------------------------------
#define B_  10
#define T_  100
#define A_  20
#define NIN 4096
#define NIMG 1024
#define NATT 512
#define NPHYS 256
#define BT  (B_*T_)            // 1000
#define NPAIR 190
#define MPAIR (BT*NPAIR)       // 190000

// Scratch (allocation-free rule: __device__ globals)
__device__ __align__(256) float g_phys[(size_t)MPAIR * NPHYS];

// ---------------------------------------------------------------------------
// PTX helpers (sm_80-class ISA — tcgen05 rejected by this toolchain)
// ---------------------------------------------------------------------------
__device__ __forceinline__ uint32_t smem_u32(const void* p) {
    uint32_t a;
    asm("{ .reg .u64 t; cvta.to.shared.u64 t, %1; cvt.u32.u64 %0, t; }"
        : "=r"(a) : "l"(p));
    return a;
}

__device__ __forceinline__ void ldsm_x4(uint32_t* r, uint32_t addr) {
    asm volatile("ldmatrix.sync.aligned.m8n8.x4.shared.b16 {%0,%1,%2,%3}, [%4];"
                 : "=r"(r[0]), "=r"(r[1]), "=r"(r[2]), "=r"(r[3]) : "r"(addr));
}

__device__ __forceinline__ uint32_t f2tf32(uint32_t x) {
    uint32_t y;
    asm("cvt.rna.tf32.f32 %0, %1;" : "=r"(y) : "f"(__uint_as_float(x)));
    return y;
}

__device__ __forceinline__ void mma_tf32(float* d, const uint32_t* a,
                                         uint32_t b0, uint32_t b1) {
    asm volatile(
        "mma.sync.aligned.m16n8k8.row.col.f32.tf32.tf32.f32 "
        "{%0,%1,%2,%3}, {%4,%5,%6,%7}, {%8,%9}, {%0,%1,%2,%3};"
        : "+f"(d[0]), "+f"(d[1]), "+f"(d[2]), "+f"(d[3])
        : "r"(a[0]), "r"(a[1]), "r"(a[2]), "r"(a[3]), "r"(b0), "r"(b1));
}

__device__ __forceinline__ void cp_async16(uint32_t dst, const void* src, int sz) {
    asm volatile("cp.async.cg.shared.global [%0], [%1], 16, %2;"
                 :: "r"(dst), "l"(src), "r"(sz));
}

// ---------------------------------------------------------------------------
// loc/glob tf32 GEMM: C[M,N] = gatherA[M,K] @ Bw[N,K]^T + bias
//   mode 1: A row r at A + r*(20*4096)                    (glob: x[:,:,0,:])
//   mode 2: A row r at A + ((r/19)*20 + r%19 + 1)*4096    (loc: x[:,:,1:,:])
// CTA 128x128, 128 threads (4 warps x 64x64 tiles), BK=32, 3-stage, 2 CTA/SM.
// ---------------------------------------------------------------------------
#define STG_A 0
#define STG_B 16384
#define STAGE_BYTES 32768
#define SM_GEMM (3 * STAGE_BYTES)   // 98304

struct GemmDesc {
    const float* A; const float* Bw; const float* bias; float* C;
    int M, N, K, mode;
};

__device__ __forceinline__ void gemm_core(const GemmDesc g, int idx, uint32_t sb)
{
    const float* __restrict__ A  = g.A;
    const float* __restrict__ Bw = g.Bw;
    const int M = g.M, N = g.N, K = g.K, mode = g.mode;

    const int nx   = N >> 7;
    const int row0 = (idx / nx) * 128;
    const int col0 = (idx % nx) * 128;

    const int tid  = threadIdx.x;
    const int wid  = tid >> 5;
    const int lane = tid & 31;
    const int wm = (wid & 1) * 64;   // warp M offset
    const int wn = (wid >> 1) * 64;  // warp N offset

    // ---- cp.async slots: 8 A-chunks + 8 B-chunks of 16B per stage ----
    long aoff[8]; int avalid[8]; uint32_t dstA[8];
    long boff[8]; uint32_t dstB[8];
    #pragma unroll
    for (int j = 0; j < 8; j++) {
        const int e = tid + j * 128;        // 0..1023
        const int r = e >> 3, kc = e & 7;
        const uint32_t sw = (uint32_t)(r * 128 + ((kc ^ (r & 7)) * 16));
        dstA[j] = sb + STG_A + sw;
        dstB[j] = sb + STG_B + sw;
        const int am = row0 + r;
        avalid[j] = (am < M) ? 16 : 0;
        const int amc = (am < M) ? am : 0;
        long ao;
        if (mode == 1) ao = (long)amc * (long)(A_ * NIN);
        else           ao = ((long)(amc / 19) * A_ + (amc % 19) + 1) * (long)NIN;
        aoff[j] = ao + kc * 4;
        boff[j] = (long)(col0 + r) * K + kc * 4;
    }

    const int arow = lane & 15;
    const int agrp = lane >> 4;
    const int brow = (lane & 7) + ((lane >> 4) << 3);
    const int bgrp = (lane >> 3) & 1;

    float d[4][8][4];
    #pragma unroll
    for (int mt = 0; mt < 4; mt++)
        #pragma unroll
        for (int nt = 0; nt < 8; nt++)
            #pragma unroll
            for (int q = 0; q < 4; q++) d[mt][nt][q] = 0.f;

    const int NK = K / 32;

    #pragma unroll
    for (int s = 0; s < 2; s++) {
        const uint32_t so = s * STAGE_BYTES;
        const int koff = s * 32;
        #pragma unroll
        for (int j = 0; j < 8; j++) {
            cp_async16(dstA[j] + so, A + aoff[j] + koff, avalid[j]);
            cp_async16(dstB[j] + so, Bw + boff[j] + koff, 16);
        }
        asm volatile("cp.async.commit_group;" ::: "memory");
    }

    #pragma unroll 1
    for (int kb = 0; kb < NK; kb++) {
        asm volatile("cp.async.wait_group 1;" ::: "memory");
        __syncthreads();

        if (kb + 2 < NK) {
            const uint32_t so = ((kb + 2) % 3) * STAGE_BYTES;
            const int koff = (kb + 2) * 32;
            #pragma unroll
            for (int j = 0; j < 8; j++) {
                cp_async16(dstA[j] + so, A + aoff[j] + koff, avalid[j]);
                cp_async16(dstB[j] + so, Bw + boff[j] + koff, 16);
            }
        }
        asm volatile("cp.async.commit_group;" ::: "memory");

        const uint32_t sa  = sb + STG_A + (kb % 3) * STAGE_BYTES;
        const uint32_t sbs = sb + STG_B + (kb % 3) * STAGE_BYTES;
        #pragma unroll
        for (int kk = 0; kk < 4; kk++) {
            uint32_t afr[4][4];
            #pragma unroll
            for (int mt = 0; mt < 4; mt++) {
                const int r = wm + mt * 16 + arow;
                ldsm_x4(afr[mt], sa + r * 128 + (((2 * kk + agrp) ^ (r & 7)) * 16));
                #pragma unroll
                for (int q = 0; q < 4; q++) afr[mt][q] = f2tf32(afr[mt][q]);
            }
            uint32_t bfr[4][4];
            #pragma unroll
            for (int nt2 = 0; nt2 < 4; nt2++) {
                const int r = wn + nt2 * 16 + brow;
                ldsm_x4(bfr[nt2], sbs + r * 128 + (((2 * kk + bgrp) ^ (r & 7)) * 16));
                #pragma unroll
                for (int q = 0; q < 4; q++) bfr[nt2][q] = f2tf32(bfr[nt2][q]);
            }
            #pragma unroll
            for (int mt = 0; mt < 4; mt++)
                #pragma unroll
                for (int nt = 0; nt < 8; nt++)
                    mma_tf32(d[mt][nt], afr[mt],
                             bfr[nt >> 1][(nt & 1) * 2], bfr[nt >> 1][(nt & 1) * 2 + 1]);
        }
    }

    float* __restrict__ C = g.C;
    const float* __restrict__ bias = g.bias;
    #pragma unroll
    for (int mt = 0; mt < 4; mt++) {
        const int rlo = row0 + wm + mt * 16 + (lane >> 2);
        const int rhi = rlo + 8;
        #pragma unroll
        for (int nt = 0; nt < 8; nt++) {
            const int col = col0 + wn + nt * 8 + (lane & 3) * 2;
            const float2 bv = *(const float2*)(bias + col);
            if (rlo < M) {
                float2 v; v.x = d[mt][nt][0] + bv.x; v.y = d[mt][nt][1] + bv.y;
                *(float2*)(C + (long)rlo * N + col) = v;
            }
            if (rhi < M) {
                float2 v; v.x = d[mt][nt][2] + bv.x; v.y = d[mt][nt][3] + bv.y;
                *(float2*)(C + (long)rhi * N + col) = v;
            }
        }
    }
}

__global__ __launch_bounds__(128, 2)
void fused_gemm(const GemmDesc d0, const GemmDesc d1, int split)
{
    extern __shared__ char smem[];
    const uint32_t sb = smem_u32(smem);
    const int i = blockIdx.x;
    if (i < split) gemm_core(d0, i, sb);
    else           gemm_core(d1, i - split, sb);
}

// ---------------------------------------------------------------------------
// Fused phys kernel: per CTA of 128 pair-rows:
//   phase 1: feat(128x32, pad 26->32) @ Wp^T (+bp, relu) -> h1 in SMEM (tf32 mma)
//   phase 2: h1(128x256) @ W3^T (+b3) -> phys to global, W3 streamed in k-chunks
// 256 threads, 8 warps (2Mx4N), warp tile 64x64. SMEM: h1 128KB + 64KB union.
// ---------------------------------------------------------------------------
#define PH_H1   0                       // 128 rows x 1024B (swizzled per 128B)
#define PH_UN   131072                  // union: feat(16K)+Wp(32K) | W3 2x32K
#define PH_FEAT (PH_UN)
#define PH_WP   (PH_UN + 16384)
#define PH_SMEM (PH_UN + 65536)         // 196608

__global__ __launch_bounds__(256, 1)
void fused_phys(const float* __restrict__ wcf,  // (BT, 20, 13)
                const float* __restrict__ Wp,   // (256, 26)
                const float* __restrict__ bp,   // (256)
                const float* __restrict__ W3,   // (256, 256)
                const float* __restrict__ b3,   // (256)
                float* __restrict__ phys)       // (MPAIR, 256)
{
    extern __shared__ char smem[];
    const uint32_t sb = smem_u32(smem);
    const int tid  = threadIdx.x;
    const int wid  = tid >> 5;
    const int lane = tid & 31;
    const int row0 = blockIdx.x * 128;
    const int wm = (wid & 1) * 64;
    const int wn = (wid >> 1) * 64;

    // ---- fill feat (128x32) swizzled; cols>=26 or invalid rows -> 0 ----
    #pragma unroll
    for (int j = 0; j < 16; j++) {
        const int e = tid + j * 256;   // 0..4095
        const int r = e >> 5, k = e & 31;
        const int row = row0 + r;
        float v = 0.f;
        if (k < 26 && row < MPAIR) {
            const int bt = row / NPAIR;
            const int p  = row % NPAIR;
            int i2 = 0, rem = p;
            while (rem >= 19 - i2) { rem -= 19 - i2; i2++; }
            const int j2 = i2 + 1 + rem;
            const int ag = (k < 13) ? i2 : j2;
            const int kk2 = (k < 13) ? k : k - 13;
            v = wcf[(long)bt * (A_ * 13) + ag * 13 + kk2];
        }
        const uint32_t addr = sb + PH_FEAT + r * 128
                            + (((k >> 2) ^ (r & 7)) * 16) + (k & 3) * 4;
        asm volatile("st.shared.f32 [%0], %1;" :: "r"(addr), "f"(v));
    }
    // ---- fill Wp (256x32) swizzled ----
    #pragma unroll
    for (int j = 0; j < 32; j++) {
        const int e = tid + j * 256;   // 0..8191
        const int n = e >> 5, k = e & 31;
        const float v = (k < 26) ? Wp[n * 26 + k] : 0.f;
        const uint32_t addr = sb + PH_WP + n * 128
                            + (((k >> 2) ^ (n & 7)) * 16) + (k & 3) * 4;
        asm volatile("st.shared.f32 [%0], %1;" :: "r"(addr), "f"(v));
    }
    __syncthreads();

    const int arow = lane & 15;
    const int agrp = lane >> 4;
    const int brow = (lane & 7) + ((lane >> 4) << 3);
    const int bgrp = (lane >> 3) & 1;

    float d[4][8][4];
    #pragma unroll
    for (int mt = 0; mt < 4; mt++)
        #pragma unroll
        for (int nt = 0; nt < 8; nt++)
            #pragma unroll
            for (int q = 0; q < 4; q++) d[mt][nt][q] = 0.f;

    // ---- phase 1 mma: K=32 (4 chunks of 8) ----
    #pragma unroll
    for (int kk = 0; kk < 4; kk++) {
        uint32_t afr[4][4];
        #pragma unroll
        for (int mt = 0; mt < 4; mt++) {
            const int r = wm + mt * 16 + arow;
            ldsm_x4(afr[mt], sb + PH_FEAT + r * 128 + (((2 * kk + agrp) ^ (r & 7)) * 16));
            #pragma unroll
            for (int q = 0; q < 4; q++) afr[mt][q] = f2tf32(afr[mt][q]);
        }
        uint32_t bfr[4][4];
        #pragma unroll
        for (int nt2 = 0; nt2 < 4; nt2++) {
            const int r = wn + nt2 * 16 + brow;
            ldsm_x4(bfr[nt2], sb + PH_WP + r * 128 + (((2 * kk + bgrp) ^ (r & 7)) * 16));
            #pragma unroll
            for (int q = 0; q < 4; q++) bfr[nt2][q] = f2tf32(bfr[nt2][q]);
        }
        #pragma unroll
        for (int mt = 0; mt < 4; mt++)
            #pragma unroll
            for (int nt = 0; nt < 8; nt++)
                mma_tf32(d[mt][nt], afr[mt],
                         bfr[nt >> 1][(nt & 1) * 2], bfr[nt >> 1][(nt & 1) * 2 + 1]);
    }

    // ---- bias + relu + store h1 to SMEM (1024B row pitch, 128B swizzle) ----
    // h1[r][c] lives at: r*1024 + (c>>5)*128 + ((kc ^ (r&7))*16) + (c&3)*4,
    // kc = (c&31)>>2 — matches the phase-2 ldmatrix read pattern below.
    #pragma unroll
    for (int mt = 0; mt < 4; mt++) {
        const int rlo = wm + mt * 16 + (lane >> 2);
        const int rhi = rlo + 8;
        #pragma unroll
        for (int nt = 0; nt < 8; nt++) {
            const int c = wn + nt * 8 + (lane & 3) * 2;
            const float2 bv = *(const float2*)(bp + c);
            const uint32_t blk = (uint32_t)(c >> 5) * 128 + (c & 3) * 4;
            const uint32_t kc = (uint32_t)((c & 31) >> 2);
            {
                float2 v;
                v.x = fmaxf(d[mt][nt][0] + bv.x, 0.f);
                v.y = fmaxf(d[mt][nt][1] + bv.y, 0.f);
                const uint32_t addr = sb + PH_H1 + rlo * 1024 + blk
                                    + ((kc ^ (rlo & 7)) * 16);
                asm volatile("st.shared.v2.f32 [%0], {%1, %2};"
                             :: "r"(addr), "f"(v.x), "f"(v.y));
            }
            {
                float2 v;
                v.x = fmaxf(d[mt][nt][2] + bv.x, 0.f);
                v.y = fmaxf(d[mt][nt][3] + bv.y, 0.f);
                const uint32_t addr = sb + PH_H1 + rhi * 1024 + blk
                                    + ((kc ^ (rhi & 7)) * 16);
                asm volatile("st.shared.v2.f32 [%0], {%1, %2};"
                             :: "r"(addr), "f"(v.x), "f"(v.y));
            }
            #pragma unroll
            for (int q = 0; q < 4; q++) d[mt][nt][q] = 0.f;
        }
    }
    __syncthreads();   // h1 ready; feat/Wp reads done -> union reusable

    // ---- phase 2: stream W3 in 8 chunks of k=32 (2-stage, 32KB each) ----
    #pragma unroll
    for (int s = 0; s < 2; s++) {
        const uint32_t so = sb + PH_UN + s * 32768;
        #pragma unroll
        for (int j = 0; j < 8; j++) {
            const int e = tid + j * 256;   // 0..2047
            const int n = e >> 3, kc = e & 7;
            cp_async16(so + n * 128 + ((kc ^ (n & 7)) * 16),
                       W3 + (long)n * 256 + s * 32 + kc * 4, 16);
        }
        asm volatile("cp.async.commit_group;" ::: "memory");
    }

    #pragma unroll 1
    for (int kb = 0; kb < 8; kb++) {
        asm volatile("cp.async.wait_group 1;" ::: "memory");
        __syncthreads();

        const uint32_t sbs = sb + PH_UN + (kb & 1) * 32768;
        #pragma unroll
        for (int kk = 0; kk < 4; kk++) {
            uint32_t afr[4][4];
            #pragma unroll
            for (int mt = 0; mt < 4; mt++) {
                const int r = wm + mt * 16 + arow;
                ldsm_x4(afr[mt], sb + PH_H1 + r * 1024 + kb * 128
                                 + (((2 * kk + agrp) ^ (r & 7)) * 16));
                #pragma unroll
                for (int q = 0; q < 4; q++) afr[mt][q] = f2tf32(afr[mt][q]);
            }
            uint32_t bfr[4][4];
            #pragma unroll
            for (int nt2 = 0; nt2 < 4; nt2++) {
                const int r = wn + nt2 * 16 + brow;
                ldsm_x4(bfr[nt2], sbs + r * 128 + (((2 * kk + bgrp) ^ (r & 7)) * 16));
                #pragma unroll
                for (int q = 0; q < 4; q++) bfr[nt2][q] = f2tf32(bfr[nt2][q]);
            }
            #pragma unroll
            for (int mt = 0; mt < 4; mt++)
                #pragma unroll
                for (int nt = 0; nt < 8; nt++)
                    mma_tf32(d[mt][nt], afr[mt],
                             bfr[nt >> 1][(nt & 1) * 2], bfr[nt >> 1][(nt & 1) * 2 + 1]);
        }
        __syncthreads();   // stage consumed before refill

        if (kb + 2 < 8) {
            const uint32_t so = sb + PH_UN + (kb & 1) * 32768;
            #pragma unroll
            for (int j = 0; j < 8; j++) {
                const int e = tid + j * 256;
                const int n = e >> 3, kc = e & 7;
                cp_async16(so + n * 128 + ((kc ^ (n & 7)) * 16),
                           W3 + (long)n * 256 + (kb + 2) * 32 + kc * 4, 16);
            }
        }
        asm volatile("cp.async.commit_group;" ::: "memory");
    }

    // ---- epilogue: bias b3, store phys to global ----
    #pragma unroll
    for (int mt = 0; mt < 4; mt++) {
        const int rlo = row0 + wm + mt * 16 + (lane >> 2);
        const int rhi = rlo + 8;
        #pragma unroll
        for (int nt = 0; nt < 8; nt++) {
            const int col = wn + nt * 8 + (lane & 3) * 2;
            const float2 bv = *(const float2*)(b3 + col);
            if (rlo < MPAIR) {
                float2 v; v.x = d[mt][nt][0] + bv.x; v.y = d[mt][nt][1] + bv.y;
                *(float2*)(phys + (long)rlo * NPHYS + col) = v;
            }
            if (rhi < MPAIR) {
                float2 v; v.x = d[mt][nt][2] + bv.x; v.y = d[mt][nt][3] + bv.y;
                *(float2*)(phys + (long)rhi * NPHYS + col) = v;
            }
        }
    }
}

// ---------------------------------------------------------------------------
// segmax: one CTA per bt, phys[bt] staged in smem, single DRAM pass.
// ---------------------------------------------------------------------------
#define SEG_SMEM (NPAIR * NPHYS * 4)   // 194560

__global__ __launch_bounds__(512, 1)
void segmax_smem(const float* __restrict__ phys,  // (MPAIR, 256)
                 float* __restrict__ out)         // (BT, 20, 256)
{
    extern __shared__ float tile[];    // [190][256]
    const int bt  = blockIdx.x;
    const int tid = threadIdx.x;
    const float4* src = (const float4*)(phys + (long)bt * NPAIR * NPHYS);

    #pragma unroll
    for (int i = 0; i < (NPAIR * NPHYS / 4 + 511) / 512; i++) {
        const int e = tid + i * 512;
        if (e < NPAIR * NPHYS / 4) ((float4*)tile)[e] = src[e];
    }
    __syncthreads();

    #pragma unroll
    for (int i = 0; i < 10; i++) {
        const int o = tid + i * 512;
        const int k = o >> 8, n = o & 255;
        float m = -CUDART_INF_F;
        #pragma unroll
        for (int other = 0; other < A_; other++) {
            if (other == k) continue;
            const int lo = (other < k) ? other : k;
            const int hi = (other < k) ? k : other;
            const int p = lo * 19 - (lo * (lo - 1)) / 2 + (hi - lo - 1);
            m = fmaxf(m, tile[p * NPHYS + n]);
        }
        out[((long)bt * A_ + k) * NPHYS + n] = m;
    }
}

// ---------------------------------------------------------------------------
extern "C" void kernel_launch(void* const* d_in, const int* in_sizes, int n_in,
                              void* d_out, int out_size)
{
    const float* x    = (const float*)d_in[0];
    const float* wcf  = (const float*)d_in[1];
    const float* Wg   = (const float*)d_in[2];
    const float* bg   = (const float*)d_in[3];
    const float* Wl   = (const float*)d_in[4];
    const float* bl   = (const float*)d_in[5];
    const float* Wp   = (const float*)d_in[6];
    const float* bp   = (const float*)d_in[7];
    const float* W3   = (const float*)d_in[8];
    const float* b3   = (const float*)d_in[9];

    float* out      = (float*)d_out;
    float* out_glob = out;                               // (1000,1024)
    float* out_loc  = out + (size_t)BT * NIMG;           // (19000,512)
    float* out_agt  = out_loc + (size_t)BT * 19 * NATT;  // (20000,256)

    float* physp = nullptr;
    cudaGetSymbolAddress((void**)&physp, g_phys);

    cudaFuncSetAttribute(fused_gemm, cudaFuncAttributeMaxDynamicSharedMemorySize, SM_GEMM);
    cudaFuncSetAttribute(fused_phys, cudaFuncAttributeMaxDynamicSharedMemorySize, PH_SMEM);
    cudaFuncSetAttribute(segmax_smem, cudaFuncAttributeMaxDynamicSharedMemorySize, SEG_SMEM);

    // fused phys chain: phys1 (mma, K=32) + phys3 (W3 streamed) in one kernel
    fused_phys<<<(MPAIR + 127) / 128, 256, PH_SMEM>>>(wcf, Wp, bp, W3, b3, physp);

    // loc + glob merged into one launch
    {
        GemmDesc dl = { x, Wl, bl, out_loc, BT * 19, NATT, NIN, 2 };
        GemmDesc dg = { x, Wg, bg, out_glob, BT, NIMG, NIN, 1 };
        const int nLoc  = (NATT / 128) * ((BT * 19 + 127) / 128);   // 4*149 = 596
        const int nGlob = (NIMG / 128) * ((BT + 127) / 128);        // 8*8   = 64
        fused_gemm<<<nLoc + nGlob, 128, SM_GEMM>>>(dl, dg, nLoc);
    }

    // per-agent segment max (smem-staged, single DRAM pass)
    segmax_smem<<<BT, 512, SEG_SMEM>>>(physp, out_agt);
}

// round 7
// speedup vs baseline: 7.5713x; 1.7822x over previous
#include <cuda_runtime.h>
#include <cuda_fp16.h>
#include <cstdint>
#include <math_constants.h>

// ---------------------------------------------------------------------------
// Problem constants
// ---------------------------------------------------------------------------
#define B_  10
#define T_  100
#define A_  20
#define NIN 4096
#define NIMG 1024
#define NATT 512
#define NPHYS 256
#define BT  (B_*T_)            // 1000
#define NPAIR 190
#define MPAIR (BT*NPAIR)       // 190000

// Scratch (allocation-free rule: __device__ globals)
__device__ __align__(256) __half g_xh [(size_t)BT * A_ * NIN];   // fp16 x
__device__ __align__(256) __half g_wlh[(size_t)NATT * NIN];      // fp16 W_loc
__device__ __align__(256) __half g_wgh[(size_t)NIMG * NIN];      // fp16 W_glob
__device__ __align__(256) __half g_w3h[NPHYS * NPHYS];           // fp16 W_phys3
__device__ __align__(256) __half g_physh[(size_t)MPAIR * NPHYS]; // fp16 phys

// ---------------------------------------------------------------------------
// PTX helpers (sm_80-class ISA — tcgen05 rejected by this toolchain)
// ---------------------------------------------------------------------------
__device__ __forceinline__ uint32_t smem_u32(const void* p) {
    uint32_t a;
    asm("{ .reg .u64 t; cvta.to.shared.u64 t, %1; cvt.u32.u64 %0, t; }"
        : "=r"(a) : "l"(p));
    return a;
}

__device__ __forceinline__ void ldsm_x4(uint32_t* r, uint32_t addr) {
    asm volatile("ldmatrix.sync.aligned.m8n8.x4.shared.b16 {%0,%1,%2,%3}, [%4];"
                 : "=r"(r[0]), "=r"(r[1]), "=r"(r[2]), "=r"(r[3]) : "r"(addr));
}

__device__ __forceinline__ void mma_f16(float* d, const uint32_t* a,
                                        uint32_t b0, uint32_t b1) {
    asm volatile(
        "mma.sync.aligned.m16n8k16.row.col.f32.f16.f16.f32 "
        "{%0,%1,%2,%3}, {%4,%5,%6,%7}, {%8,%9}, {%0,%1,%2,%3};"
        : "+f"(d[0]), "+f"(d[1]), "+f"(d[2]), "+f"(d[3])
        : "r"(a[0]), "r"(a[1]), "r"(a[2]), "r"(a[3]), "r"(b0), "r"(b1));
}

__device__ __forceinline__ void cp_async16(uint32_t dst, const void* src, int sz) {
    asm volatile("cp.async.cg.shared.global [%0], [%1], 16, %2;"
                 :: "r"(dst), "l"(src), "r"(sz));
}

// ---------------------------------------------------------------------------
// fp32 -> fp16 convert (grid-stride, float4 -> 2x half2)
// ---------------------------------------------------------------------------
__global__ void cvt_f2h(const float* __restrict__ src, __half* __restrict__ dst,
                        int n4)
{
    const int stride = gridDim.x * blockDim.x;
    for (int i = blockIdx.x * blockDim.x + threadIdx.x; i < n4; i += stride) {
        const float4 v = ((const float4*)src)[i];
        ((__half2*)dst)[2 * i + 0] = __floats2half2_rn(v.x, v.y);
        ((__half2*)dst)[2 * i + 1] = __floats2half2_rn(v.z, v.w);
    }
}

// ---------------------------------------------------------------------------
// fp16 GEMM: C[M,N] = gatherA[M,K] @ Bw[N,K]^T + bias (fp32 out)
//   mode 1: A row r at r*(20*4096)                    (glob: x[:,:,0,:])
//   mode 2: A row r at ((r/19)*20 + r%19 + 1)*4096    (loc: x[:,:,1:,:])
// CTA 128x128, 128 threads (4 warps x 64x64), BK=64, 3-stage, 2 CTA/SM.
// smem rows: 64 halves = 128B, standard 16B-chunk XOR swizzle.
// ---------------------------------------------------------------------------
#define STG_A 0
#define STG_B 16384
#define STAGE_BYTES 32768
#define SM_GEMM (3 * STAGE_BYTES)   // 98304

struct GemmDesc {
    const __half* A; const __half* Bw; const float* bias; float* C;
    int M, N, K, mode;
};

__device__ __forceinline__ void gemm_core(const GemmDesc g, int idx, uint32_t sb)
{
    const __half* __restrict__ A  = g.A;
    const __half* __restrict__ Bw = g.Bw;
    const int M = g.M, N = g.N, K = g.K, mode = g.mode;

    const int nx   = N >> 7;
    const int row0 = (idx / nx) * 128;
    const int col0 = (idx % nx) * 128;

    const int tid  = threadIdx.x;
    const int wid  = tid >> 5;
    const int lane = tid & 31;
    const int wm = (wid & 1) * 64;
    const int wn = (wid >> 1) * 64;

    // ---- cp.async slots: 8 A-chunks + 8 B-chunks of 16B per stage ----
    long aoff[8]; int avalid[8]; uint32_t dstA[8];
    long boff[8]; uint32_t dstB[8];
    #pragma unroll
    for (int j = 0; j < 8; j++) {
        const int e = tid + j * 128;        // 0..1023
        const int r = e >> 3, kc = e & 7;   // row, 16B chunk (8 halves)
        const uint32_t sw = (uint32_t)(r * 128 + ((kc ^ (r & 7)) * 16));
        dstA[j] = sb + STG_A + sw;
        dstB[j] = sb + STG_B + sw;
        const int am = row0 + r;
        avalid[j] = (am < M) ? 16 : 0;
        const int amc = (am < M) ? am : 0;
        long ao;
        if (mode == 1) ao = (long)amc * (long)(A_ * NIN);
        else           ao = ((long)(amc / 19) * A_ + (amc % 19) + 1) * (long)NIN;
        aoff[j] = ao + kc * 8;
        boff[j] = (long)(col0 + r) * K + kc * 8;
    }

    const int arow = lane & 15;
    const int agrp = lane >> 4;
    const int brow = (lane & 7) + ((lane >> 4) << 3);
    const int bgrp = (lane >> 3) & 1;

    float d[4][8][4];
    #pragma unroll
    for (int mt = 0; mt < 4; mt++)
        #pragma unroll
        for (int nt = 0; nt < 8; nt++)
            #pragma unroll
            for (int q = 0; q < 4; q++) d[mt][nt][q] = 0.f;

    const int NK = K >> 6;   // BK = 64

    #pragma unroll
    for (int s = 0; s < 2; s++) {
        const uint32_t so = s * STAGE_BYTES;
        const int koff = s * 64;
        #pragma unroll
        for (int j = 0; j < 8; j++) {
            cp_async16(dstA[j] + so, A + aoff[j] + koff, avalid[j]);
            cp_async16(dstB[j] + so, Bw + boff[j] + koff, 16);
        }
        asm volatile("cp.async.commit_group;" ::: "memory");
    }

    #pragma unroll 1
    for (int kb = 0; kb < NK; kb++) {
        asm volatile("cp.async.wait_group 1;" ::: "memory");
        __syncthreads();

        if (kb + 2 < NK) {
            const uint32_t so = ((kb + 2) % 3) * STAGE_BYTES;
            const int koff = (kb + 2) * 64;
            #pragma unroll
            for (int j = 0; j < 8; j++) {
                cp_async16(dstA[j] + so, A + aoff[j] + koff, avalid[j]);
                cp_async16(dstB[j] + so, Bw + boff[j] + koff, 16);
            }
        }
        asm volatile("cp.async.commit_group;" ::: "memory");

        const uint32_t sa  = sb + STG_A + (kb % 3) * STAGE_BYTES;
        const uint32_t sbs = sb + STG_B + (kb % 3) * STAGE_BYTES;
        #pragma unroll
        for (int kk = 0; kk < 4; kk++) {     // 4 x k16 = BK 64
            uint32_t afr[4][4];
            #pragma unroll
            for (int mt = 0; mt < 4; mt++) {
                const int r = wm + mt * 16 + arow;
                ldsm_x4(afr[mt], sa + r * 128 + (((2 * kk + agrp) ^ (r & 7)) * 16));
            }
            uint32_t bfr[4][4];
            #pragma unroll
            for (int nt2 = 0; nt2 < 4; nt2++) {
                const int r = wn + nt2 * 16 + brow;
                ldsm_x4(bfr[nt2], sbs + r * 128 + (((2 * kk + bgrp) ^ (r & 7)) * 16));
            }
            #pragma unroll
            for (int mt = 0; mt < 4; mt++)
                #pragma unroll
                for (int nt = 0; nt < 8; nt++)
                    mma_f16(d[mt][nt], afr[mt],
                            bfr[nt >> 1][(nt & 1) * 2], bfr[nt >> 1][(nt & 1) * 2 + 1]);
        }
    }

    float* __restrict__ C = g.C;
    const float* __restrict__ bias = g.bias;
    #pragma unroll
    for (int mt = 0; mt < 4; mt++) {
        const int rlo = row0 + wm + mt * 16 + (lane >> 2);
        const int rhi = rlo + 8;
        #pragma unroll
        for (int nt = 0; nt < 8; nt++) {
            const int col = col0 + wn + nt * 8 + (lane & 3) * 2;
            const float2 bv = *(const float2*)(bias + col);
            if (rlo < M) {
                float2 v; v.x = d[mt][nt][0] + bv.x; v.y = d[mt][nt][1] + bv.y;
                *(float2*)(C + (long)rlo * N + col) = v;
            }
            if (rhi < M) {
                float2 v; v.x = d[mt][nt][2] + bv.x; v.y = d[mt][nt][3] + bv.y;
                *(float2*)(C + (long)rhi * N + col) = v;
            }
        }
    }
}

__global__ __launch_bounds__(128, 2)
void fused_gemm(const GemmDesc d0, const GemmDesc d1, int split)
{
    extern __shared__ char smem[];
    const uint32_t sb = smem_u32(smem);
    const int i = blockIdx.x;
    if (i < split) gemm_core(d0, i, sb);
    else           gemm_core(d1, i - split, sb);
}

// ---------------------------------------------------------------------------
// Fused phys kernel (fp16 operands): per CTA of 128 pair-rows:
//  phase 1: feat(128x32f16, pad26) @ Wp^T (+bp, relu) -> h1 fp16 in SMEM
//  phase 2: h1(128x256) @ W3^T (+b3) -> phys fp16 to global (W3 streamed)
// 256 threads, 8 warps (2Mx4N, 64x64 tiles).
// SMEM: h1 64KB + union{feat 16KB + Wp 32KB | W3 2x32KB} = 128KB.
// ---------------------------------------------------------------------------
#define PH_H1   0                       // 128 rows x 512B
#define PH_UN   65536
#define PH_FEAT (PH_UN)                 // 128 x 128B
#define PH_WP   (PH_UN + 16384)         // 256 x 128B
#define PH_SMEM (PH_UN + 65536)         // 131072

__global__ __launch_bounds__(256, 1)
void fused_phys(const float* __restrict__ wcf,  // (BT, 20, 13) fp32
                const float* __restrict__ Wp,   // (256, 26) fp32
                const float* __restrict__ bp,   // (256)
                const __half* __restrict__ W3h, // (256, 256) fp16
                const float* __restrict__ b3,   // (256)
                __half* __restrict__ phys)      // (MPAIR, 256) fp16
{
    extern __shared__ char smem[];
    const uint32_t sb = smem_u32(smem);
    const int tid  = threadIdx.x;
    const int wid  = tid >> 5;
    const int lane = tid & 31;
    const int row0 = blockIdx.x * 128;
    const int wm = (wid & 1) * 64;
    const int wn = (wid >> 1) * 64;

    // ---- fill feat (128 x 32 halves, zeros for k>=26 / invalid rows) ----
    #pragma unroll
    for (int j = 0; j < 16; j++) {
        const int e = tid + j * 256;   // 0..4095
        const int r = e >> 5, k = e & 31;
        const int row = row0 + r;
        float v = 0.f;
        if (k < 26 && row < MPAIR) {
            const int bt = row / NPAIR;
            const int p  = row % NPAIR;
            int i2 = 0, rem = p;
            while (rem >= 19 - i2) { rem -= 19 - i2; i2++; }
            const int j2 = i2 + 1 + rem;
            const int ag = (k < 13) ? i2 : j2;
            const int kk2 = (k < 13) ? k : k - 13;
            v = wcf[(long)bt * (A_ * 13) + ag * 13 + kk2];
        }
        const __half h = __float2half_rn(v);
        const unsigned short hs = *(const unsigned short*)&h;
        const uint32_t addr = sb + PH_FEAT + r * 128
                            + (((k >> 3) ^ (r & 7)) * 16) + (k & 7) * 2;
        asm volatile("st.shared.u16 [%0], %1;" :: "r"(addr), "h"(hs));
    }
    // ---- fill Wp (256 x 32 halves) ----
    #pragma unroll
    for (int j = 0; j < 32; j++) {
        const int e = tid + j * 256;   // 0..8191
        const int n = e >> 5, k = e & 31;
        const float v = (k < 26) ? Wp[n * 26 + k] : 0.f;
        const __half h = __float2half_rn(v);
        const unsigned short hs = *(const unsigned short*)&h;
        const uint32_t addr = sb + PH_WP + n * 128
                            + (((k >> 3) ^ (n & 7)) * 16) + (k & 7) * 2;
        asm volatile("st.shared.u16 [%0], %1;" :: "r"(addr), "h"(hs));
    }
    __syncthreads();

    const int arow = lane & 15;
    const int agrp = lane >> 4;
    const int brow = (lane & 7) + ((lane >> 4) << 3);
    const int bgrp = (lane >> 3) & 1;

    float d[4][8][4];
    #pragma unroll
    for (int mt = 0; mt < 4; mt++)
        #pragma unroll
        for (int nt = 0; nt < 8; nt++)
            #pragma unroll
            for (int q = 0; q < 4; q++) d[mt][nt][q] = 0.f;

    // ---- phase 1 mma: K=32 -> kk = 0,1 (k16 each) ----
    #pragma unroll
    for (int kk = 0; kk < 2; kk++) {
        uint32_t afr[4][4];
        #pragma unroll
        for (int mt = 0; mt < 4; mt++) {
            const int r = wm + mt * 16 + arow;
            ldsm_x4(afr[mt], sb + PH_FEAT + r * 128 + (((2 * kk + agrp) ^ (r & 7)) * 16));
        }
        uint32_t bfr[4][4];
        #pragma unroll
        for (int nt2 = 0; nt2 < 4; nt2++) {
            const int r = wn + nt2 * 16 + brow;
            ldsm_x4(bfr[nt2], sb + PH_WP + r * 128 + (((2 * kk + bgrp) ^ (r & 7)) * 16));
        }
        #pragma unroll
        for (int mt = 0; mt < 4; mt++)
            #pragma unroll
            for (int nt = 0; nt < 8; nt++)
                mma_f16(d[mt][nt], afr[mt],
                        bfr[nt >> 1][(nt & 1) * 2], bfr[nt >> 1][(nt & 1) * 2 + 1]);
    }

    // ---- bias + relu -> h1 fp16 to SMEM (512B row pitch, 16B XOR swizzle) ----
    // h1[r][c]: r*512 + (c>>6)*128 + (((c&63)>>3 ^ (r&7))*16) + (c&7)*2
    #pragma unroll
    for (int mt = 0; mt < 4; mt++) {
        const int rlo = wm + mt * 16 + (lane >> 2);
        const int rhi = rlo + 8;
        #pragma unroll
        for (int nt = 0; nt < 8; nt++) {
            const int c = wn + nt * 8 + (lane & 3) * 2;
            const float2 bv = *(const float2*)(bp + c);
            const uint32_t blk = (uint32_t)(c >> 6) * 128 + (c & 7) * 2;
            const uint32_t kc = (uint32_t)((c & 63) >> 3);
            {
                const __half2 h = __floats2half2_rn(fmaxf(d[mt][nt][0] + bv.x, 0.f),
                                                    fmaxf(d[mt][nt][1] + bv.y, 0.f));
                const uint32_t u = *(const uint32_t*)&h;
                const uint32_t addr = sb + PH_H1 + rlo * 512 + blk
                                    + ((kc ^ (rlo & 7)) * 16);
                asm volatile("st.shared.u32 [%0], %1;" :: "r"(addr), "r"(u));
            }
            {
                const __half2 h = __floats2half2_rn(fmaxf(d[mt][nt][2] + bv.x, 0.f),
                                                    fmaxf(d[mt][nt][3] + bv.y, 0.f));
                const uint32_t u = *(const uint32_t*)&h;
                const uint32_t addr = sb + PH_H1 + rhi * 512 + blk
                                    + ((kc ^ (rhi & 7)) * 16);
                asm volatile("st.shared.u32 [%0], %1;" :: "r"(addr), "r"(u));
            }
            #pragma unroll
            for (int q = 0; q < 4; q++) d[mt][nt][q] = 0.f;
        }
    }
    __syncthreads();   // h1 ready; feat/Wp region reusable for W3

    // ---- phase 2: stream W3 fp16 in 4 chunks of k=64 (2-stage, 32KB) ----
    #pragma unroll
    for (int s = 0; s < 2; s++) {
        const uint32_t so = sb + PH_UN + s * 32768;
        #pragma unroll
        for (int j = 0; j < 8; j++) {
            const int e = tid + j * 256;   // 0..2047
            const int n = e >> 3, kc = e & 7;
            cp_async16(so + n * 128 + ((kc ^ (n & 7)) * 16),
                       W3h + (long)n * 256 + s * 64 + kc * 8, 16);
        }
        asm volatile("cp.async.commit_group;" ::: "memory");
    }

    #pragma unroll 1
    for (int kb = 0; kb < 4; kb++) {
        asm volatile("cp.async.wait_group 1;" ::: "memory");
        __syncthreads();

        const uint32_t sbs = sb + PH_UN + (kb & 1) * 32768;
        #pragma unroll
        for (int kk = 0; kk < 4; kk++) {
            uint32_t afr[4][4];
            #pragma unroll
            for (int mt = 0; mt < 4; mt++) {
                const int r = wm + mt * 16 + arow;
                ldsm_x4(afr[mt], sb + PH_H1 + r * 512 + kb * 128
                                 + (((2 * kk + agrp) ^ (r & 7)) * 16));
            }
            uint32_t bfr[4][4];
            #pragma unroll
            for (int nt2 = 0; nt2 < 4; nt2++) {
                const int r = wn + nt2 * 16 + brow;
                ldsm_x4(bfr[nt2], sbs + r * 128 + (((2 * kk + bgrp) ^ (r & 7)) * 16));
            }
            #pragma unroll
            for (int mt = 0; mt < 4; mt++)
                #pragma unroll
                for (int nt = 0; nt < 8; nt++)
                    mma_f16(d[mt][nt], afr[mt],
                            bfr[nt >> 1][(nt & 1) * 2], bfr[nt >> 1][(nt & 1) * 2 + 1]);
        }
        __syncthreads();   // stage consumed before refill

        if (kb + 2 < 4) {
            const uint32_t so = sb + PH_UN + (kb & 1) * 32768;
            #pragma unroll
            for (int j = 0; j < 8; j++) {
                const int e = tid + j * 256;
                const int n = e >> 3, kc = e & 7;
                cp_async16(so + n * 128 + ((kc ^ (n & 7)) * 16),
                           W3h + (long)n * 256 + (kb + 2) * 64 + kc * 8, 16);
            }
        }
        asm volatile("cp.async.commit_group;" ::: "memory");
    }

    // ---- epilogue: + b3, convert to fp16, store phys ----
    #pragma unroll
    for (int mt = 0; mt < 4; mt++) {
        const int rlo = row0 + wm + mt * 16 + (lane >> 2);
        const int rhi = rlo + 8;
        #pragma unroll
        for (int nt = 0; nt < 8; nt++) {
            const int col = wn + nt * 8 + (lane & 3) * 2;
            const float2 bv = *(const float2*)(b3 + col);
            if (rlo < MPAIR) {
                const __half2 h = __floats2half2_rn(d[mt][nt][0] + bv.x,
                                                    d[mt][nt][1] + bv.y);
                *(__half2*)(phys + (long)rlo * NPHYS + col) = h;
            }
            if (rhi < MPAIR) {
                const __half2 h = __floats2half2_rn(d[mt][nt][2] + bv.x,
                                                    d[mt][nt][3] + bv.y);
                *(__half2*)(phys + (long)rhi * NPHYS + col) = h;
            }
        }
    }
}

// ---------------------------------------------------------------------------
// segmax: one CTA per bt, fp16 phys staged in smem (97KB), fp32 out.
// ---------------------------------------------------------------------------
#define SEG_SMEM (NPAIR * NPHYS * 2)   // 97280

__global__ __launch_bounds__(512, 2)
void segmax_smem(const __half* __restrict__ phys,  // (MPAIR, 256) fp16
                 float* __restrict__ out)          // (BT, 20, 256) fp32
{
    extern __shared__ __half tile[];   // [190][256] fp16
    const int bt  = blockIdx.x;
    const int tid = threadIdx.x;
    const uint4* src = (const uint4*)(phys + (long)bt * NPAIR * NPHYS);

    const int n16 = NPAIR * NPHYS * 2 / 16;   // 6080 uint4s
    #pragma unroll
    for (int i = 0; i < 12; i++) {
        const int e = tid + i * 512;
        if (e < n16) ((uint4*)tile)[e] = src[e];
    }
    __syncthreads();

    #pragma unroll
    for (int i = 0; i < 10; i++) {
        const int o = tid + i * 512;
        const int k = o >> 8, n = o & 255;
        float m = -CUDART_INF_F;
        #pragma unroll
        for (int other = 0; other < A_; other++) {
            if (other == k) continue;
            const int lo = (other < k) ? other : k;
            const int hi = (other < k) ? k : other;
            const int p = lo * 19 - (lo * (lo - 1)) / 2 + (hi - lo - 1);
            m = fmaxf(m, __half2float(tile[p * NPHYS + n]));
        }
        out[((long)bt * A_ + k) * NPHYS + n] = m;
    }
}

// ---------------------------------------------------------------------------
extern "C" void kernel_launch(void* const* d_in, const int* in_sizes, int n_in,
                              void* d_out, int out_size)
{
    const float* x    = (const float*)d_in[0];
    const float* wcf  = (const float*)d_in[1];
    const float* Wg   = (const float*)d_in[2];
    const float* bg   = (const float*)d_in[3];
    const float* Wl   = (const float*)d_in[4];
    const float* bl   = (const float*)d_in[5];
    const float* Wp   = (const float*)d_in[6];
    const float* bp   = (const float*)d_in[7];
    const float* W3   = (const float*)d_in[8];
    const float* b3   = (const float*)d_in[9];

    float* out      = (float*)d_out;
    float* out_glob = out;                               // (1000,1024)
    float* out_loc  = out + (size_t)BT * NIMG;           // (19000,512)
    float* out_agt  = out_loc + (size_t)BT * 19 * NATT;  // (20000,256)

    __half *xh, *wlh, *wgh, *w3h, *physh;
    cudaGetSymbolAddress((void**)&xh,    g_xh);
    cudaGetSymbolAddress((void**)&wlh,   g_wlh);
    cudaGetSymbolAddress((void**)&wgh,   g_wgh);
    cudaGetSymbolAddress((void**)&w3h,   g_w3h);
    cudaGetSymbolAddress((void**)&physh, g_physh);

    cudaFuncSetAttribute(fused_gemm, cudaFuncAttributeMaxDynamicSharedMemorySize, SM_GEMM);
    cudaFuncSetAttribute(fused_phys, cudaFuncAttributeMaxDynamicSharedMemorySize, PH_SMEM);
    cudaFuncSetAttribute(segmax_smem, cudaFuncAttributeMaxDynamicSharedMemorySize, SEG_SMEM);

    // fp32 -> fp16 conversion pre-pass
    cvt_f2h<<<2048, 256>>>(x,  xh,  (BT * A_ * NIN) / 4);
    cvt_f2h<<<256, 256>>>(Wl, wlh, (NATT * NIN) / 4);
    cvt_f2h<<<256, 256>>>(Wg, wgh, (NIMG * NIN) / 4);
    cvt_f2h<<<64,  256>>>(W3, w3h, (NPHYS * NPHYS) / 4);

    // fused phys chain (phys1 mma + phys3 with W3 streamed), fp16 phys out
    fused_phys<<<(MPAIR + 127) / 128, 256, PH_SMEM>>>(wcf, Wp, bp, w3h, b3, physh);

    // loc + glob merged into one fp16 GEMM launch
    {
        GemmDesc dl = { xh, wlh, bl, out_loc, BT * 19, NATT, NIN, 2 };
        GemmDesc dg = { xh, wgh, bg, out_glob, BT, NIMG, NIN, 1 };
        const int nLoc  = (NATT / 128) * ((BT * 19 + 127) / 128);   // 596
        const int nGlob = (NIMG / 128) * ((BT + 127) / 128);        // 64
        fused_gemm<<<nLoc + nGlob, 128, SM_GEMM>>>(dl, dg, nLoc);
    }

    // per-agent segment max (fp16 in, fp32 out)
    segmax_smem<<<BT, 512, SEG_SMEM>>>(physh, out_agt);
}